// round 1
// baseline (speedup 1.0000x reference)
#include <cuda_runtime.h>
#include <cstdint>

// Problem constants
#define N_SENT 65536
#define D_DIM  2304
#define N_BAGS 4096
#define C_CLS  53
#define C_PAD  56      // padded class dim (multiple of 7*8 mapping)
#define BM     128     // rows per block
#define BK     16      // k-slice per tile
#define NTHR   128
#define NT     (D_DIM / BK)   // 144 k-tiles

typedef unsigned long long ull;

// Scratch (static device arrays; no allocations allowed)
__device__ float2 g_Wt2[D_DIM * C_PAD];                 // W^T, zero-padded, value-duplicated (w,w)
__device__ float  g_probs[(size_t)N_SENT * C_CLS];      // softmax probs for all sentences
__device__ ull    g_best[N_BAGS];                       // packed (lp_bits<<32)|~row per bag

__device__ __forceinline__ void ffma2(ull &d, ull a, ull b) {
    // packed 2-wide fp32 FMA (sm_100+): d.lo += a.lo*b.lo ; d.hi += a.hi*b.hi
    asm volatile("fma.rn.f32x2 %0, %1, %2, %0;" : "+l"(d) : "l"(a), "l"(b));
}

// ---------------------------------------------------------------------------
// Kernel 1: transpose W -> Wt2 (duplicated float2, zero-padded cols) + zero g_best
// ---------------------------------------------------------------------------
__global__ void prep_kernel(const float* __restrict__ W) {
    int idx = blockIdx.x * blockDim.x + threadIdx.x;
    if (idx < D_DIM * C_PAD) {
        int k = idx / C_PAD;
        int c = idx - k * C_PAD;
        float w = (c < C_CLS) ? W[c * D_DIM + k] : 0.0f;
        g_Wt2[idx] = make_float2(w, w);
    }
    if (idx < N_BAGS) g_best[idx] = 0ull;
}

// ---------------------------------------------------------------------------
// Kernel 2: fused GEMM (f32x2) + bias + softmax + per-bag packed atomicMax
// ---------------------------------------------------------------------------
struct GemmBufs {
    float  As[2][BK][BM];     // A tile, transposed [k][m]
    float2 Bs[2][BK][C_PAD];  // B tile, duplicated (w,w)
};
union SmemU {
    GemmBufs g;
    float logits[BM][57];     // 57: pad to avoid bank conflicts in row scans
};

__global__ __launch_bounds__(NTHR)
void main_kernel(const float* __restrict__ reps,
                 const int*   __restrict__ scope,
                 const int*   __restrict__ label,
                 const float* __restrict__ bias) {
    __shared__ __align__(16) SmemU sm;
    __shared__ float inv_sum[BM];

    const int tid = threadIdx.x;
    const int rowBase = blockIdx.x * BM;

    // compute mapping: 16 m-groups x 8 n-groups; per thread 8 rows x 7 cols
    const int tm = tid >> 3;          // 0..15
    const int tn = tid & 7;           // 0..7
    const int m0 = tm * 8;
    const int n0 = tn * 7;

    // A-load mapping: 4 threads per row (one float4 each), 32 rows per pass
    const int a_row = tid >> 2;       // 0..31
    const int a_q   = tid & 3;        // which float4 within the 16-float k-chunk

    ull acc[7][4];
    #pragma unroll
    for (int j = 0; j < 7; j++)
        #pragma unroll
        for (int i = 0; i < 4; i++) acc[j][i] = 0ull;

    const float* a_base = reps + (size_t)(rowBase + a_row) * D_DIM + 4 * a_q;

    float4 ra[4];
    float2 rb[7];

    // ---- prologue: load + store tile 0 ----
    #pragma unroll
    for (int i = 0; i < 4; i++)
        ra[i] = *(const float4*)(a_base + (size_t)(32 * i) * D_DIM);
    {
        const float2* bsrc = g_Wt2;   // tile 0
        #pragma unroll
        for (int i = 0; i < 7; i++) rb[i] = bsrc[tid + 128 * i];
    }
    #pragma unroll
    for (int i = 0; i < 4; i++) {
        int r = a_row + 32 * i;
        sm.g.As[0][4 * a_q + 0][r] = ra[i].x;
        sm.g.As[0][4 * a_q + 1][r] = ra[i].y;
        sm.g.As[0][4 * a_q + 2][r] = ra[i].z;
        sm.g.As[0][4 * a_q + 3][r] = ra[i].w;
    }
    {
        float2* bd = &sm.g.Bs[0][0][0];
        #pragma unroll
        for (int i = 0; i < 7; i++) bd[tid + 128 * i] = rb[i];
    }
    __syncthreads();

    // ---- main loop: double-buffered ----
    for (int t = 0; t < NT; t++) {
        const int buf = t & 1;
        const bool more = (t + 1 < NT);
        if (more) {
            const float* ap = a_base + (t + 1) * BK;
            #pragma unroll
            for (int i = 0; i < 4; i++)
                ra[i] = *(const float4*)(ap + (size_t)(32 * i) * D_DIM);
            const float2* bsrc = g_Wt2 + (t + 1) * BK * C_PAD;
            #pragma unroll
            for (int i = 0; i < 7; i++) rb[i] = bsrc[tid + 128 * i];
        }

        #pragma unroll
        for (int k = 0; k < BK; k++) {
            ulonglong2 p0 = *(const ulonglong2*)&sm.g.As[buf][k][m0];
            ulonglong2 p1 = *(const ulonglong2*)&sm.g.As[buf][k][m0 + 4];
            ull a2[4];
            a2[0] = p0.x; a2[1] = p0.y; a2[2] = p1.x; a2[3] = p1.y;
            #pragma unroll
            for (int j = 0; j < 7; j++) {
                ull b2 = *(const ull*)&sm.g.Bs[buf][k][n0 + j];
                ffma2(acc[j][0], a2[0], b2);
                ffma2(acc[j][1], a2[1], b2);
                ffma2(acc[j][2], a2[2], b2);
                ffma2(acc[j][3], a2[3], b2);
            }
        }

        if (more) {
            const int nb = buf ^ 1;
            #pragma unroll
            for (int i = 0; i < 4; i++) {
                int r = a_row + 32 * i;
                sm.g.As[nb][4 * a_q + 0][r] = ra[i].x;
                sm.g.As[nb][4 * a_q + 1][r] = ra[i].y;
                sm.g.As[nb][4 * a_q + 2][r] = ra[i].z;
                sm.g.As[nb][4 * a_q + 3][r] = ra[i].w;
            }
            float2* bd = &sm.g.Bs[nb][0][0];
            #pragma unroll
            for (int i = 0; i < 7; i++) bd[tid + 128 * i] = rb[i];
        }
        __syncthreads();
    }

    // ---- epilogue: logits -> smem (with bias) ----
    float bj[7];
    #pragma unroll
    for (int j = 0; j < 7; j++) {
        int c = n0 + j;
        bj[j] = (c < C_CLS) ? bias[c] : 0.0f;
    }
    #pragma unroll
    for (int j = 0; j < 7; j++) {
        #pragma unroll
        for (int i = 0; i < 4; i++) {
            float vx, vy;
            asm("mov.b64 {%0, %1}, %2;" : "=f"(vx), "=f"(vy) : "l"(acc[j][i]));
            sm.logits[m0 + 2 * i][n0 + j]     = vx + bj[j];
            sm.logits[m0 + 2 * i + 1][n0 + j] = vy + bj[j];
        }
    }
    __syncthreads();

    // ---- per-row softmax + bag argmax (thread r <-> row r) ----
    {
        const int r = tid;
        float mx = -1e30f;
        for (int c = 0; c < C_CLS; c++) mx = fmaxf(mx, sm.logits[r][c]);
        float s = 0.0f;
        for (int c = 0; c < C_CLS; c++) {
            float e = expf(sm.logits[r][c] - mx);
            sm.logits[r][c] = e;
            s += e;
        }
        float is = 1.0f / s;
        inv_sum[r] = is;

        const int row = rowBase + r;
        // bag id: largest i with scope[i] <= row
        int lo = 0, hi = N_BAGS;
        while (hi - lo > 1) {
            int mid = (lo + hi) >> 1;
            if (scope[mid] <= row) lo = mid; else hi = mid;
        }
        const int lbl = label[lo];
        const float lp = sm.logits[r][lbl] * is;
        // pack: higher lp wins; ties -> smaller row index (matches reference)
        ull pk = ((ull)__float_as_uint(lp) << 32) | (unsigned)(~row);
        atomicMax(&g_best[lo], pk);
    }
    __syncthreads();

    // ---- coalesced prob write ----
    for (int idx = tid; idx < BM * C_CLS; idx += NTHR) {
        int rr = idx / C_CLS;
        int cc = idx - rr * C_CLS;
        g_probs[(size_t)rowBase * C_CLS + idx] = sm.logits[rr][cc] * inv_sum[rr];
    }
}

// ---------------------------------------------------------------------------
// Kernel 3: gather selected rows
// ---------------------------------------------------------------------------
__global__ void gather_kernel(float* __restrict__ out) {
    int idx = blockIdx.x * blockDim.x + threadIdx.x;
    if (idx < N_BAGS * C_CLS) {
        int b = idx / C_CLS;
        int c = idx - b * C_CLS;
        unsigned sel = ~(unsigned)g_best[b];   // recover row index
        out[idx] = g_probs[(size_t)sel * C_CLS + c];
    }
}

// ---------------------------------------------------------------------------
extern "C" void kernel_launch(void* const* d_in, const int* in_sizes, int n_in,
                              void* d_out, int out_size) {
    const float* reps  = (const float*)d_in[0];
    const int*   scope = (const int*)  d_in[1];
    const int*   label = (const int*)  d_in[2];
    const float* W     = (const float*)d_in[3];
    const float* b     = (const float*)d_in[4];
    float* out = (float*)d_out;

    prep_kernel<<<(D_DIM * C_PAD + 255) / 256, 256>>>(W);
    main_kernel<<<N_SENT / BM, NTHR>>>(reps, scope, label, b);
    gather_kernel<<<(N_BAGS * C_CLS + 255) / 256, 256>>>(out);
}

// round 2
// speedup vs baseline: 2.2960x; 2.2960x over previous
#include <cuda_runtime.h>
#include <cuda_fp16.h>
#include <cstdint>

// Problem constants
#define N_SENT 65536
#define D_DIM  2304
#define N_BAGS 4096
#define C_CLS  53
#define N_PAD  64          // padded class dim
#define BM     128         // rows per CTA
#define KC     64          // k per smem stage
#define NCHUNK (D_DIM / KC)   // 36
#define NTHR   256

typedef unsigned long long ull;

// ------------- global scratch (no allocs allowed) -------------
__device__ __half g_BtH[N_PAD * D_DIM];   // W^T as [n][k], f16 hi
__device__ __half g_BtL[N_PAD * D_DIM];   // f16 lo residual
__device__ float  g_probs[(size_t)N_SENT * C_CLS];
__device__ ull    g_best[N_BAGS];

// ------------- smem layout (dynamic) -------------
#define A_STRIDE 72        // halves per row (64 + 8 pad -> conflict-free ldmatrix)
#define B_STRIDE 72
#define A_STAGE  (128 * A_STRIDE)      // halves
#define B_STAGE  (64 * B_STRIDE)
#define OFF_AH   0
#define SZ_AH    (2 * A_STAGE * 2)     // bytes: 36864
#define OFF_AL   (OFF_AH + SZ_AH)
#define OFF_BH   (OFF_AL + SZ_AH)      // 73728
#define SZ_BH    (2 * B_STAGE * 2)     // 18432
#define OFF_BL   (OFF_BH + SZ_BH)
#define SMEM_TOTAL (OFF_BL + SZ_BH)    // 110592 bytes
// epilogue overlay
#define L_STRIDE 65
#define OFF_LOGITS 0                   // 128*65*4 = 33280
#define OFF_INVSUM 33280               // + 512

__device__ __forceinline__ void ldm4(uint32_t* r, uint32_t addr) {
    asm volatile("ldmatrix.sync.aligned.m8n8.x4.shared.b16 {%0,%1,%2,%3}, [%4];\n"
                 : "=r"(r[0]), "=r"(r[1]), "=r"(r[2]), "=r"(r[3]) : "r"(addr));
}

__device__ __forceinline__ void mma16816(float* c, const uint32_t* a,
                                         uint32_t b0, uint32_t b1) {
    asm volatile(
        "mma.sync.aligned.m16n8k16.row.col.f32.f16.f16.f32 "
        "{%0,%1,%2,%3}, {%4,%5,%6,%7}, {%8,%9}, {%0,%1,%2,%3};\n"
        : "+f"(c[0]), "+f"(c[1]), "+f"(c[2]), "+f"(c[3])
        : "r"(a[0]), "r"(a[1]), "r"(a[2]), "r"(a[3]), "r"(b0), "r"(b1));
}

// ---------------------------------------------------------------------------
// Kernel 1: W -> W^T f16 hi/lo splits (zero-padded rows) + zero g_best
// ---------------------------------------------------------------------------
__global__ void prep_kernel(const float* __restrict__ W) {
    int idx = blockIdx.x * blockDim.x + threadIdx.x;
    if (idx < N_PAD * D_DIM) {
        int n = idx / D_DIM;
        int k = idx - n * D_DIM;
        float w = (n < C_CLS) ? W[n * D_DIM + k] : 0.0f;
        __half h = __float2half_rn(w);
        float lo = w - __half2float(h);
        g_BtH[idx] = h;
        g_BtL[idx] = __float2half_rn(lo);
    }
    if (idx < N_BAGS) g_best[idx] = 0ull;
}

// ---------------------------------------------------------------------------
// Kernel 2: fused split-f16 tensor GEMM + bias + softmax + bag argmax
// ---------------------------------------------------------------------------
__global__ __launch_bounds__(NTHR)
void main_kernel(const float* __restrict__ reps,
                 const int*   __restrict__ scope,
                 const int*   __restrict__ label,
                 const float* __restrict__ bias) {
    extern __shared__ char smem[];
    __half* Ah = (__half*)(smem + OFF_AH);
    __half* Al = (__half*)(smem + OFF_AL);
    __half* Bh = (__half*)(smem + OFF_BH);
    __half* Bl = (__half*)(smem + OFF_BL);
    float* logits  = (float*)(smem + OFF_LOGITS);
    float* inv_sum = (float*)(smem + OFF_INVSUM);

    const int tid  = threadIdx.x;
    const int lane = tid & 31;
    const int wrp  = tid >> 5;          // 0..7
    const int rowBase = blockIdx.x * BM;
    const int mbase = wrp * 16;

    float acc[8][4];
    #pragma unroll
    for (int j = 0; j < 8; j++)
        #pragma unroll
        for (int i = 0; i < 4; i++) acc[j][i] = 0.0f;

    // global-load thread mapping
    const int ldRow = tid >> 4;         // 0..15
    const int ldCol = tid & 15;         // 0..15
    const float*  aPtr  = reps  + (size_t)(rowBase + ldRow) * D_DIM + ldCol * 4;
    const __half* bhPtr = g_BtH + (size_t)ldRow * D_DIM + ldCol * 4;
    const __half* blPtr = g_BtL + (size_t)ldRow * D_DIM + ldCol * 4;

    float4 ra[8];
    uint2  rbh[4], rbl[4];

    // ldmatrix source addresses (per-thread constants modulo stage/kstep offset)
    const int aLdmOff = (mbase + (lane & 15)) * A_STRIDE + ((lane >> 4) << 3);
    const int bRowOff = (lane & 7) + ((lane >> 4) << 3);
    const int bColOff = ((lane >> 3) & 1) << 3;

    // ---- prologue: load + convert + store chunk 0 ----
    #pragma unroll
    for (int i = 0; i < 8; i++)
        ra[i] = *(const float4*)(aPtr + (size_t)(16 * i) * D_DIM);
    #pragma unroll
    for (int i = 0; i < 4; i++) {
        rbh[i] = *(const uint2*)(bhPtr + (size_t)(16 * i) * D_DIM);
        rbl[i] = *(const uint2*)(blPtr + (size_t)(16 * i) * D_DIM);
    }
    {
        #pragma unroll
        for (int i = 0; i < 8; i++) {
            int r = ldRow + 16 * i;
            __half2 h01 = __floats2half2_rn(ra[i].x, ra[i].y);
            __half2 h23 = __floats2half2_rn(ra[i].z, ra[i].w);
            float lx = ra[i].x - __half2float(__low2half(h01));
            float ly = ra[i].y - __half2float(__high2half(h01));
            float lz = ra[i].z - __half2float(__low2half(h23));
            float lw = ra[i].w - __half2float(__high2half(h23));
            __half2 l01 = __floats2half2_rn(lx, ly);
            __half2 l23 = __floats2half2_rn(lz, lw);
            uint2 uh; uh.x = *(uint32_t*)&h01; uh.y = *(uint32_t*)&h23;
            uint2 ul; ul.x = *(uint32_t*)&l01; ul.y = *(uint32_t*)&l23;
            *(uint2*)(Ah + r * A_STRIDE + ldCol * 4) = uh;
            *(uint2*)(Al + r * A_STRIDE + ldCol * 4) = ul;
        }
        #pragma unroll
        for (int i = 0; i < 4; i++) {
            int r = ldRow + 16 * i;
            *(uint2*)(Bh + r * B_STRIDE + ldCol * 4) = rbh[i];
            *(uint2*)(Bl + r * B_STRIDE + ldCol * 4) = rbl[i];
        }
    }
    __syncthreads();

    // ---- main loop ----
    for (int t = 0; t < NCHUNK; t++) {
        const int buf = t & 1;
        const bool more = (t + 1 < NCHUNK);
        if (more) {
            const int ko = (t + 1) * KC;
            #pragma unroll
            for (int i = 0; i < 8; i++)
                ra[i] = *(const float4*)(aPtr + (size_t)(16 * i) * D_DIM + ko);
            #pragma unroll
            for (int i = 0; i < 4; i++) {
                rbh[i] = *(const uint2*)(bhPtr + (size_t)(16 * i) * D_DIM + ko);
                rbl[i] = *(const uint2*)(blPtr + (size_t)(16 * i) * D_DIM + ko);
            }
        }

        const __half* ah = Ah + buf * A_STAGE;
        const __half* al = Al + buf * A_STAGE;
        const __half* bh = Bh + buf * B_STAGE;
        const __half* bl = Bl + buf * B_STAGE;

        #pragma unroll
        for (int s = 0; s < 4; s++) {
            uint32_t afh[4], afl[4];
            uint32_t aadr = (uint32_t)__cvta_generic_to_shared(ah + aLdmOff + s * 16);
            uint32_t ladr = (uint32_t)__cvta_generic_to_shared(al + aLdmOff + s * 16);
            ldm4(afh, aadr);
            ldm4(afl, ladr);

            uint32_t bfh[16], bfl[16];
            #pragma unroll
            for (int p = 0; p < 4; p++) {
                int boff = (16 * p + bRowOff) * B_STRIDE + s * 16 + bColOff;
                ldm4(&bfh[4 * p], (uint32_t)__cvta_generic_to_shared(bh + boff));
                ldm4(&bfl[4 * p], (uint32_t)__cvta_generic_to_shared(bl + boff));
            }

            #pragma unroll
            for (int j = 0; j < 8; j++) mma16816(acc[j], afh, bfh[2 * j], bfh[2 * j + 1]);
            #pragma unroll
            for (int j = 0; j < 8; j++) mma16816(acc[j], afh, bfl[2 * j], bfl[2 * j + 1]);
            #pragma unroll
            for (int j = 0; j < 8; j++) mma16816(acc[j], afl, bfh[2 * j], bfh[2 * j + 1]);
        }

        if (more) {
            const int nb = (t + 1) & 1;
            __half* dAh = Ah + nb * A_STAGE;
            __half* dAl = Al + nb * A_STAGE;
            __half* dBh = Bh + nb * B_STAGE;
            __half* dBl = Bl + nb * B_STAGE;
            #pragma unroll
            for (int i = 0; i < 8; i++) {
                int r = ldRow + 16 * i;
                __half2 h01 = __floats2half2_rn(ra[i].x, ra[i].y);
                __half2 h23 = __floats2half2_rn(ra[i].z, ra[i].w);
                float lx = ra[i].x - __half2float(__low2half(h01));
                float ly = ra[i].y - __half2float(__high2half(h01));
                float lz = ra[i].z - __half2float(__low2half(h23));
                float lw = ra[i].w - __half2float(__high2half(h23));
                __half2 l01 = __floats2half2_rn(lx, ly);
                __half2 l23 = __floats2half2_rn(lz, lw);
                uint2 uh; uh.x = *(uint32_t*)&h01; uh.y = *(uint32_t*)&h23;
                uint2 ul; ul.x = *(uint32_t*)&l01; ul.y = *(uint32_t*)&l23;
                *(uint2*)(dAh + r * A_STRIDE + ldCol * 4) = uh;
                *(uint2*)(dAl + r * A_STRIDE + ldCol * 4) = ul;
            }
            #pragma unroll
            for (int i = 0; i < 4; i++) {
                int r = ldRow + 16 * i;
                *(uint2*)(dBh + r * B_STRIDE + ldCol * 4) = rbh[i];
                *(uint2*)(dBl + r * B_STRIDE + ldCol * 4) = rbl[i];
            }
        }
        __syncthreads();
    }

    // ---- epilogue: acc + bias -> logits smem ----
    {
        const int r0 = mbase + (lane >> 2);
        const int cb = (lane & 3) * 2;
        #pragma unroll
        for (int j = 0; j < 8; j++) {
            int c = j * 8 + cb;
            float b0 = (c     < C_CLS) ? bias[c]     : 0.0f;
            float b1 = (c + 1 < C_CLS) ? bias[c + 1] : 0.0f;
            logits[r0 * L_STRIDE + c]           = acc[j][0] + b0;
            logits[r0 * L_STRIDE + c + 1]       = acc[j][1] + b1;
            logits[(r0 + 8) * L_STRIDE + c]     = acc[j][2] + b0;
            logits[(r0 + 8) * L_STRIDE + c + 1] = acc[j][3] + b1;
        }
    }
    __syncthreads();

    // ---- per-row softmax + bag argmax (threads 0..127 <-> rows) ----
    if (tid < BM) {
        const int r = tid;
        float* lrow = logits + r * L_STRIDE;
        float mx = -1e30f;
        for (int c = 0; c < C_CLS; c++) mx = fmaxf(mx, lrow[c]);
        float s = 0.0f;
        for (int c = 0; c < C_CLS; c++) {
            float e = expf(lrow[c] - mx);
            lrow[c] = e;
            s += e;
        }
        float is = 1.0f / s;
        inv_sum[r] = is;

        const int row = rowBase + r;
        int lo = 0, hi = N_BAGS;
        while (hi - lo > 1) {
            int mid = (lo + hi) >> 1;
            if (scope[mid] <= row) lo = mid; else hi = mid;
        }
        const int lbl = label[lo];
        const float lp = lrow[lbl] * is;
        ull pk = ((ull)__float_as_uint(lp) << 32) | (unsigned)(~row);
        atomicMax(&g_best[lo], pk);
    }
    __syncthreads();

    // ---- coalesced prob write ----
    for (int idx = tid; idx < BM * C_CLS; idx += NTHR) {
        int rr = idx / C_CLS;
        int cc = idx - rr * C_CLS;
        g_probs[(size_t)rowBase * C_CLS + idx] = logits[rr * L_STRIDE + cc] * inv_sum[rr];
    }
}

// ---------------------------------------------------------------------------
// Kernel 3: gather selected rows
// ---------------------------------------------------------------------------
__global__ void gather_kernel(float* __restrict__ out) {
    int idx = blockIdx.x * blockDim.x + threadIdx.x;
    if (idx < N_BAGS * C_CLS) {
        int b = idx / C_CLS;
        int c = idx - b * C_CLS;
        unsigned sel = ~(unsigned)g_best[b];
        out[idx] = g_probs[(size_t)sel * C_CLS + c];
    }
}

// ---------------------------------------------------------------------------
extern "C" void kernel_launch(void* const* d_in, const int* in_sizes, int n_in,
                              void* d_out, int out_size) {
    const float* reps  = (const float*)d_in[0];
    const int*   scope = (const int*)  d_in[1];
    const int*   label = (const int*)  d_in[2];
    const float* W     = (const float*)d_in[3];
    const float* b     = (const float*)d_in[4];
    float* out = (float*)d_out;

    cudaFuncSetAttribute(main_kernel,
                         cudaFuncAttributeMaxDynamicSharedMemorySize, SMEM_TOTAL);

    prep_kernel<<<(N_PAD * D_DIM + 255) / 256, 256>>>(W);
    main_kernel<<<N_SENT / BM, NTHR, SMEM_TOTAL>>>(reps, scope, label, b);
    gather_kernel<<<(N_BAGS * C_CLS + 255) / 256, 256>>>(out);
}